// round 10
// baseline (speedup 1.0000x reference)
#include <cuda_runtime.h>
#include <cuda_bf16.h>
#include <cstdint>

// Problem constants
#define Bn  4
#define Nn  2048
#define Dn  512
#define Hn  8
#define HDn 64
#define MT  (Bn*Nn)   // 8192 rows

// Scratch (allocation-free rule: __device__ globals)
__device__ __nv_bfloat16 g_xh[MT*Dn], g_xl[MT*Dn];           // input q split
__device__ __nv_bfloat16 g_wh[4*Dn*Dn], g_wl[4*Dn*Dn];       // Wq,Wk,Wv,Wo split
__device__ __nv_bfloat16 g_qh[MT*Dn], g_ql[MT*Dn];           // Q proj (scaled 1/8)
__device__ __nv_bfloat16 g_kh[MT*Dn], g_kl[MT*Dn];           // K proj [tok][dim]
__device__ __nv_bfloat16 g_vth[MT*Dn], g_vtl[MT*Dn];         // V proj transposed [(b,h,d)][tok]
__device__ __nv_bfloat16 g_oh[MT*Dn], g_ol[MT*Dn];           // attention output split
__device__ float g_maskf[Bn*Nn];

// ===========================================================================
// common helpers
// ===========================================================================
__device__ __forceinline__ uint32_t smem_u32(const void* p) {
    uint32_t a;
    asm("{ .reg .u64 t; cvta.to.shared.u64 t, %1; cvt.u32.u64 %0, t; }" : "=r"(a) : "l"(p));
    return a;
}
__device__ __forceinline__ void mma_bf16(float* c, const uint32_t* a, const uint32_t* b) {
    asm volatile("mma.sync.aligned.m16n8k16.row.col.f32.bf16.bf16.f32 "
        "{%0,%1,%2,%3}, {%4,%5,%6,%7}, {%8,%9}, {%0,%1,%2,%3};"
        : "+f"(c[0]), "+f"(c[1]), "+f"(c[2]), "+f"(c[3])
        : "r"(a[0]), "r"(a[1]), "r"(a[2]), "r"(a[3]), "r"(b[0]), "r"(b[1]));
}
__device__ __forceinline__ void ldm_x4(uint32_t* r, uint32_t saddr) {
    asm volatile("ldmatrix.sync.aligned.m8n8.x4.shared.b16 {%0,%1,%2,%3}, [%4];"
        : "=r"(r[0]), "=r"(r[1]), "=r"(r[2]), "=r"(r[3]) : "r"(saddr));
}
__device__ __forceinline__ void cp16(uint32_t saddr, const void* g) {
    asm volatile("cp.async.ca.shared.global [%0], [%1], 16;" :: "r"(saddr), "l"(g));
}
__device__ __forceinline__ void cp_commit() { asm volatile("cp.async.commit_group;" ::: "memory"); }
__device__ __forceinline__ void cp_wait0()  { asm volatile("cp.async.wait_group 0;" ::: "memory"); }
__device__ __forceinline__ void cp_wait1()  { asm volatile("cp.async.wait_group 1;" ::: "memory"); }

__device__ __forceinline__ uint32_t packbf_hi(float x, float y, float& rx, float& ry) {
    __nv_bfloat16 hx = __float2bfloat16(x), hy = __float2bfloat16(y);
    rx = x - __bfloat162float(hx);
    ry = y - __bfloat162float(hy);
    return (uint32_t)__bfloat16_as_ushort(hx) | ((uint32_t)__bfloat16_as_ushort(hy) << 16);
}
__device__ __forceinline__ uint32_t packbf(float x, float y) {
    return (uint32_t)__bfloat16_as_ushort(__float2bfloat16(x)) |
           ((uint32_t)__bfloat16_as_ushort(__float2bfloat16(y)) << 16);
}
__device__ __forceinline__ void packhl(float x, float y, uint32_t& h, uint32_t& l) {
    float rx, ry;
    h = packbf_hi(x, y, rx, ry);
    l = packbf(rx, ry);
}

// ===========================================================================
// prep: mask -> float addend; fp32 -> bf16 hi/lo split
// ===========================================================================
__global__ void mask_prep(const int* __restrict__ mask) {
    int i = blockIdx.x * blockDim.x + threadIdx.x;
    if (i < Bn * Nn) g_maskf[i] = mask[i] ? -1e30f : 0.0f;
}

__global__ void prep_split_x(const float4* __restrict__ src) {
    int i = blockIdx.x * blockDim.x + threadIdx.x;      // over MT*Dn/4
    float4 v = src[i];
    float r0, r1, r2, r3;
    uint32_t h0 = packbf_hi(v.x, v.y, r0, r1);
    uint32_t h1 = packbf_hi(v.z, v.w, r2, r3);
    reinterpret_cast<uint2*>(g_xh)[i] = make_uint2(h0, h1);
    reinterpret_cast<uint2*>(g_xl)[i] = make_uint2(packbf(r0, r1), packbf(r2, r3));
}

__global__ void prep_split_w(const float4* __restrict__ w0, const float4* __restrict__ w1,
                             const float4* __restrict__ w2, const float4* __restrict__ w3) {
    int i = blockIdx.x * blockDim.x + threadIdx.x;      // over Dn*Dn/4
    int z = blockIdx.y;
    const float4* src = (z == 0) ? w0 : (z == 1) ? w1 : (z == 2) ? w2 : w3;
    float4 v = src[i];
    float r0, r1, r2, r3;
    uint32_t h0 = packbf_hi(v.x, v.y, r0, r1);
    uint32_t h1 = packbf_hi(v.z, v.w, r2, r3);
    size_t o = (size_t)z * (Dn * Dn / 4) + i;
    reinterpret_cast<uint2*>(g_wh)[o] = make_uint2(h0, h1);
    reinterpret_cast<uint2*>(g_wl)[o] = make_uint2(packbf(r0, r1), packbf(r2, r3));
}

// ===========================================================================
// bf16x3 GEMM mainloop on PRE-SPLIT inputs: CTA 256 thr, tile 128x128, BK=32,
// 2-stage cp.async double buffer, ldmatrix loads, independent-sweep MMAs.
// ===========================================================================
#define BK    32
#define SAstr 40
#define ARR_B (128*SAstr*2)         // 10240 B per array
#define STG_B (4*ARR_B)             // 40960 B per stage
#define SMEM_GEMM (2*STG_B)         // 81920 B
#define NCH   (Dn/BK)               // 16

#define GEMM_MAINLOOP(AH, AL, BH, BL, ACC) \
    const uint32_t sU = smem_u32(smg); \
    const __nv_bfloat16* Ah_g = (AH) + (size_t)m0 * Dn; \
    const __nv_bfloat16* Al_g = (AL) + (size_t)m0 * Dn; \
    const __nv_bfloat16* Bh_g = (BH) + (size_t)n0 * Dn; \
    const __nv_bfloat16* Bl_g = (BL) + (size_t)n0 * Dn; \
    auto prefetch = [&](int kc) { \
        const uint32_t u = sU + (kc & 1) * STG_B; \
        _Pragma("unroll") \
        for (int t = 0; t < 2; t++) { \
            int id = tid + t * 256; \
            int row = id >> 2, c = id & 3; \
            size_t go = (size_t)row * Dn + kc * BK + c * 8; \
            uint32_t so = u + row * (SAstr * 2) + c * 16; \
            cp16(so,             Ah_g + go); \
            cp16(so + ARR_B,     Al_g + go); \
            cp16(so + 2 * ARR_B, Bh_g + go); \
            cp16(so + 3 * ARR_B, Bl_g + go); \
        } \
        cp_commit(); \
    }; \
    prefetch(0); \
    _Pragma("unroll 1") \
    for (int kc = 0; kc < NCH; kc++) { \
        if (kc + 1 < NCH) { prefetch(kc + 1); cp_wait1(); } else { cp_wait0(); } \
        __syncthreads(); \
        const uint32_t s = sU + (kc & 1) * STG_B; \
        _Pragma("unroll") \
        for (int ks = 0; ks < 2; ks++) { \
            const int k0 = ks * 16; \
            uint32_t ah[2][4], al[2][4]; \
            _Pragma("unroll") \
            for (int t = 0; t < 2; t++) { \
                uint32_t ra = wm + t * 16 + (lane & 15); \
                uint32_t ad = s + (ra * SAstr + k0 + (lane >> 4) * 8) * 2; \
                ldm_x4(ah[t], ad); \
                ldm_x4(al[t], ad + ARR_B); \
            } \
            _Pragma("unroll") \
            for (int jp = 0; jp < 2; jp++) { \
                uint32_t bh[2][4], bl[2][4]; \
                _Pragma("unroll") \
                for (int qq = 0; qq < 2; qq++) { \
                    int jj = 2 * jp + qq; \
                    uint32_t rb = wn + 8 * (2 * jj + ((lane >> 4) & 1)) + (lane & 7); \
                    uint32_t ad = s + 2 * ARR_B + (rb * SAstr + k0 + ((lane >> 3) & 1) * 8) * 2; \
                    ldm_x4(bh[qq], ad); \
                    ldm_x4(bl[qq], ad + ARR_B); \
                } \
                /* sweep 1: hi*hi — 8 independent accumulators */ \
                _Pragma("unroll") \
                for (int qq = 0; qq < 2; qq++) \
                    _Pragma("unroll") \
                    for (int t = 0; t < 2; t++) { \
                        mma_bf16(ACC[t][4 * jp + 2 * qq],     ah[t], &bh[qq][0]); \
                        mma_bf16(ACC[t][4 * jp + 2 * qq + 1], ah[t], &bh[qq][2]); \
                    } \
                /* sweep 2: hi*lo */ \
                _Pragma("unroll") \
                for (int qq = 0; qq < 2; qq++) \
                    _Pragma("unroll") \
                    for (int t = 0; t < 2; t++) { \
                        mma_bf16(ACC[t][4 * jp + 2 * qq],     ah[t], &bl[qq][0]); \
                        mma_bf16(ACC[t][4 * jp + 2 * qq + 1], ah[t], &bl[qq][2]); \
                    } \
                /* sweep 3: lo*hi */ \
                _Pragma("unroll") \
                for (int qq = 0; qq < 2; qq++) \
                    _Pragma("unroll") \
                    for (int t = 0; t < 2; t++) { \
                        mma_bf16(ACC[t][4 * jp + 2 * qq],     al[t], &bh[qq][0]); \
                        mma_bf16(ACC[t][4 * jp + 2 * qq + 1], al[t], &bh[qq][2]); \
                    } \
            } \
        } \
        __syncthreads(); \
    }

// ---------------------------------------------------------------------------
// QKV projection GEMM: z=0 Q (scaled 1/8), z=1 K, z=2 V (smem-transposed)
// ---------------------------------------------------------------------------
#define TSTR 136     // V-transpose smem: tokens per d-row (272 B, 16B-mult)
#define TARR (128*TSTR*2)   // 34816 B

__global__ __launch_bounds__(256, 2) void gemm_qkv() {
    extern __shared__ __align__(16) char smg[];
    const int tid  = threadIdx.x;
    const int lane = tid & 31;
    const int g    = lane >> 2;
    const int tg   = lane & 3;
    const int wid  = tid >> 5;
    const int n0 = blockIdx.x * 128, m0 = blockIdx.y * 128;
    const int z  = blockIdx.z;
    const int wm = (wid & 3) * 32;
    const int wn = (wid >> 2) * 64;

    float acc[2][8][4];
    #pragma unroll
    for (int t = 0; t < 2; t++)
        #pragma unroll
        for (int j = 0; j < 8; j++)
            #pragma unroll
            for (int e = 0; e < 4; e++) acc[t][j][e] = 0.0f;

    const __nv_bfloat16* Wh = g_wh + (size_t)z * Dn * Dn;
    const __nv_bfloat16* Wl = g_wl + (size_t)z * Dn * Dn;
    GEMM_MAINLOOP(g_xh, g_xl, Wh, Wl, acc)

    if (z < 2) {
        __nv_bfloat16* Oh = (z == 0) ? g_qh : g_kh;
        __nv_bfloat16* Ol = (z == 0) ? g_ql : g_kl;
        const float sc = (z == 0) ? 0.125f : 1.0f;
        #pragma unroll
        for (int t = 0; t < 2; t++)
            #pragma unroll
            for (int j = 0; j < 8; j++) {
                int r = m0 + wm + t * 16 + g;
                int c = n0 + wn + j * 8 + tg * 2;
                float v0 = acc[t][j][0] * sc, v1 = acc[t][j][1] * sc;
                float v2 = acc[t][j][2] * sc, v3 = acc[t][j][3] * sc;
                uint32_t h, l;
                packhl(v0, v1, h, l);
                *reinterpret_cast<uint32_t*>(&Oh[(size_t)r * Dn + c]) = h;
                *reinterpret_cast<uint32_t*>(&Ol[(size_t)r * Dn + c]) = l;
                packhl(v2, v3, h, l);
                *reinterpret_cast<uint32_t*>(&Oh[(size_t)(r + 8) * Dn + c]) = h;
                *reinterpret_cast<uint32_t*>(&Ol[(size_t)(r + 8) * Dn + c]) = l;
            }
    } else {
        // V: transpose through smem, then coalesced writes to g_vt[h|l]
        #pragma unroll
        for (int t = 0; t < 2; t++)
            #pragma unroll
            for (int j = 0; j < 8; j++)
                #pragma unroll
                for (int e = 0; e < 4; e++) {
                    int lr = wm + t * 16 + g + (e >> 1) * 8;        // local token
                    int lc = wn + j * 8 + tg * 2 + (e & 1);         // local dim
                    float v = acc[t][j][e];
                    __nv_bfloat16 hv = __float2bfloat16(v);
                    *reinterpret_cast<__nv_bfloat16*>(smg + (size_t)lc * (TSTR * 2) + lr * 2) = hv;
                    *reinterpret_cast<__nv_bfloat16*>(smg + TARR + (size_t)lc * (TSTR * 2) + lr * 2) =
                        __float2bfloat16(v - __bfloat162float(hv));
                }
        __syncthreads();
        const int dd = tid >> 1;            // 0..127 (local dim)
        const int hf = tid & 1;             // half of 128 tokens
        const int b  = m0 >> 11;
        const int hh = (n0 + dd) >> 6;
        const int d  = (n0 + dd) & 63;
        const size_t dst = (((size_t)(b * Hn + hh)) * HDn + d) * Nn + (m0 & (Nn - 1)) + hf * 64;
        const uint32_t so = (uint32_t)dd * (TSTR * 2) + hf * 128;
        #pragma unroll
        for (int u = 0; u < 8; u++) {
            *reinterpret_cast<uint4*>(&g_vth[dst + u * 8]) =
                *reinterpret_cast<const uint4*>(smg + so + u * 16);
            *reinterpret_cast<uint4*>(&g_vtl[dst + u * 8]) =
                *reinterpret_cast<const uint4*>(smg + TARR + so + u * 16);
        }
    }
}

// ---------------------------------------------------------------------------
// Output projection GEMM: reads pre-split O, writes fp32
// ---------------------------------------------------------------------------
__global__ __launch_bounds__(256, 2) void gemm_out(float* __restrict__ C) {
    extern __shared__ __align__(16) char smg[];
    const int tid  = threadIdx.x;
    const int lane = tid & 31;
    const int g    = lane >> 2;
    const int tg   = lane & 3;
    const int wid  = tid >> 5;
    const int n0 = blockIdx.x * 128, m0 = blockIdx.y * 128;
    const int wm = (wid & 3) * 32;
    const int wn = (wid >> 2) * 64;

    float acc[2][8][4];
    #pragma unroll
    for (int t = 0; t < 2; t++)
        #pragma unroll
        for (int j = 0; j < 8; j++)
            #pragma unroll
            for (int e = 0; e < 4; e++) acc[t][j][e] = 0.0f;

    const __nv_bfloat16* Wh = g_wh + (size_t)3 * Dn * Dn;
    const __nv_bfloat16* Wl = g_wl + (size_t)3 * Dn * Dn;
    GEMM_MAINLOOP(g_oh, g_ol, Wh, Wl, acc)

    #pragma unroll
    for (int t = 0; t < 2; t++)
        #pragma unroll
        for (int j = 0; j < 8; j++) {
            int row = m0 + wm + t * 16 + g;
            int col = n0 + wn + j * 8 + tg * 2;
            *reinterpret_cast<float2*>(C + (size_t)row * Dn + col) =
                make_float2(acc[t][j][0], acc[t][j][1]);
            *reinterpret_cast<float2*>(C + (size_t)(row + 8) * Dn + col) =
                make_float2(acc[t][j][2], acc[t][j][3]);
        }
}

// ===========================================================================
// Tensor-core flash attention: 128 q-rows per CTA (8 warps x 16 rows),
// k-tiles of 64 keys, bf16x3 S and PV, cp.async double buffer, 2 CTAs/SM.
// Independent-sweep MMA ordering to break accumulator RAW chains.
// ===========================================================================
#define KSTR 144
#define VSTR 144
#define KARR (64*KSTR)
#define VARR (64*VSTR)
#define VOFF (2*KARR)
#define MOFF (2*KARR + 2*VARR)
#define STG_ATT (MOFF + 256)
#define SMEM_ATT (2*STG_ATT)

__global__ __launch_bounds__(256, 2) void attn_mma(const float* __restrict__ bias) {
    extern __shared__ __align__(16) char sma[];
    const uint32_t sb = smem_u32(sma);
    const int tid  = threadIdx.x;
    const int lane = tid & 31;
    const int w    = tid >> 5;
    const int g    = lane >> 2;
    const int tg   = lane & 3;
    const int h  = blockIdx.x;
    const int q0 = blockIdx.y * 128;
    const int b  = blockIdx.z;

    // ---- Q fragments from gmem (once) ----
    uint32_t qh[4][4], ql[4][4];
    {
        const size_t rbase = (size_t)(b * Nn + q0 + w * 16) * Dn + h * HDn;
        #pragma unroll
        for (int c = 0; c < 4; c++) {
            size_t o0 = rbase + (size_t)g * Dn + c * 16 + tg * 2;
            size_t o1 = rbase + (size_t)(g + 8) * Dn + c * 16 + tg * 2;
            qh[c][0] = *reinterpret_cast<const uint32_t*>(&g_qh[o0]);
            qh[c][1] = *reinterpret_cast<const uint32_t*>(&g_qh[o1]);
            qh[c][2] = *reinterpret_cast<const uint32_t*>(&g_qh[o0 + 8]);
            qh[c][3] = *reinterpret_cast<const uint32_t*>(&g_qh[o1 + 8]);
            ql[c][0] = *reinterpret_cast<const uint32_t*>(&g_ql[o0]);
            ql[c][1] = *reinterpret_cast<const uint32_t*>(&g_ql[o1]);
            ql[c][2] = *reinterpret_cast<const uint32_t*>(&g_ql[o0 + 8]);
            ql[c][3] = *reinterpret_cast<const uint32_t*>(&g_ql[o1 + 8]);
        }
    }

    const char* kh_base = (const char*)g_kh + ((size_t)(b * Nn) * Dn + h * HDn) * 2;
    const char* kl_base = (const char*)g_kl + ((size_t)(b * Nn) * Dn + h * HDn) * 2;
    const char* vh_base = (const char*)g_vth + ((size_t)(b * Hn + h) * HDn) * Nn * 2;
    const char* vl_base = (const char*)g_vtl + ((size_t)(b * Hn + h) * HDn) * Nn * 2;
    const char* mk_base = (const char*)g_maskf + (size_t)(b * Nn) * 4;

    auto prefetch = [&](int kt) {
        const uint32_t u = sb + (kt & 1) * STG_ATT;
        const size_t kof = (size_t)kt * 64 * (Dn * 2);
        #pragma unroll
        for (int t = 0; t < 2; t++) {
            int id = tid + t * 256;
            int row = id >> 3, c = id & 7;
            cp16(u + row * KSTR + c * 16,        kh_base + kof + (size_t)row * (Dn * 2) + c * 16);
            cp16(u + KARR + row * KSTR + c * 16, kl_base + kof + (size_t)row * (Dn * 2) + c * 16);
            cp16(u + VOFF + row * VSTR + c * 16,
                 vh_base + (size_t)row * (Nn * 2) + kt * 128 + c * 16);
            cp16(u + VOFF + VARR + row * VSTR + c * 16,
                 vl_base + (size_t)row * (Nn * 2) + kt * 128 + c * 16);
        }
        if (tid < 16) cp16(u + MOFF + tid * 16, mk_base + (size_t)kt * 256 + tid * 16);
        cp_commit();
    };

    float O[8][4];
    #pragma unroll
    for (int j = 0; j < 8; j++)
        #pragma unroll
        for (int e = 0; e < 4; e++) O[j][e] = 0.0f;
    float m0r = -3e38f, m1r = -3e38f, l0 = 0.0f, l1 = 0.0f;

    prefetch(0);

    const float* bb = bias + ((size_t)(b * Nn) + q0 + w * 16) * Nn;

    #pragma unroll 1
    for (int kt = 0; kt < Nn / 64; kt++) {
        cp_wait0();
        __syncthreads();
        const uint32_t ub = sb + (kt & 1) * STG_ATT;
        if (kt + 1 < Nn / 64) prefetch(kt + 1);

        // ---- S = Q K^T (bf16x3), pair-batched independent sweeps ----
        float Sf[8][4];
        #pragma unroll
        for (int j = 0; j < 8; j++)
            #pragma unroll
            for (int e = 0; e < 4; e++) Sf[j][e] = 0.0f;

        #pragma unroll
        for (int c = 0; c < 4; c++) {
            #pragma unroll
            for (int pp = 0; pp < 2; pp++) {
                uint32_t bh[2][4], bl[2][4];
                #pragma unroll
                for (int uu = 0; uu < 2; uu++) {
                    const int jp = 2 * pp + uu;
                    const int mrow = 8 * (2 * jp + ((lane >> 4) & 1)) + (lane & 7);
                    const int mcol = 16 * c + ((lane >> 3) & 1) * 8;
                    const uint32_t ad = ub + mrow * KSTR + mcol * 2;
                    ldm_x4(bh[uu], ad);
                    ldm_x4(bl[uu], ad + KARR);
                }
                // sweep hh (4 independent)
                #pragma unroll
                for (int uu = 0; uu < 2; uu++) {
                    mma_bf16(Sf[4 * pp + 2 * uu],     qh[c], &bh[uu][0]);
                    mma_bf16(Sf[4 * pp + 2 * uu + 1], qh[c], &bh[uu][2]);
                }
                // sweep hl
                #pragma unroll
                for (int uu = 0; uu < 2; uu++) {
                    mma_bf16(Sf[4 * pp + 2 * uu],     qh[c], &bl[uu][0]);
                    mma_bf16(Sf[4 * pp + 2 * uu + 1], qh[c], &bl[uu][2]);
                }
                // sweep lh
                #pragma unroll
                for (int uu = 0; uu < 2; uu++) {
                    mma_bf16(Sf[4 * pp + 2 * uu],     ql[c], &bh[uu][0]);
                    mma_bf16(Sf[4 * pp + 2 * uu + 1], ql[c], &bh[uu][2]);
                }
            }
        }

        // ---- bias + mask ----
        const float* bt = bb + (size_t)kt * 64;
        #pragma unroll
        for (int j = 0; j < 8; j++) {
            float2 mv = *reinterpret_cast<const float2*>(sma + (kt & 1) * STG_ATT + MOFF
                                                         + (8 * j + 2 * tg) * 4);
            float2 bv0 = *reinterpret_cast<const float2*>(bt + (size_t)g * Nn + 8 * j + 2 * tg);
            float2 bv1 = *reinterpret_cast<const float2*>(bt + (size_t)(g + 8) * Nn + 8 * j + 2 * tg);
            Sf[j][0] += bv0.x + mv.x; Sf[j][1] += bv0.y + mv.y;
            Sf[j][2] += bv1.x + mv.x; Sf[j][3] += bv1.y + mv.y;
        }

        // ---- online softmax on fragments ----
        float mx0 = -3e38f, mx1 = -3e38f;
        #pragma unroll
        for (int j = 0; j < 8; j++) {
            mx0 = fmaxf(mx0, fmaxf(Sf[j][0], Sf[j][1]));
            mx1 = fmaxf(mx1, fmaxf(Sf[j][2], Sf[j][3]));
        }
        #pragma unroll
        for (int off = 1; off < 4; off <<= 1) {
            mx0 = fmaxf(mx0, __shfl_xor_sync(0xffffffffu, mx0, off));
            mx1 = fmaxf(mx1, __shfl_xor_sync(0xffffffffu, mx1, off));
        }
        const float mn0 = fmaxf(m0r, mx0), mn1 = fmaxf(m1r, mx1);
        const float sc0 = __expf(m0r - mn0), sc1 = __expf(m1r - mn1);
        m0r = mn0; m1r = mn1;
        float sum0 = 0.0f, sum1 = 0.0f;
        #pragma unroll
        for (int j = 0; j < 8; j++) {
            Sf[j][0] = __expf(Sf[j][0] - mn0);
            Sf[j][1] = __expf(Sf[j][1] - mn0);
            Sf[j][2] = __expf(Sf[j][2] - mn1);
            Sf[j][3] = __expf(Sf[j][3] - mn1);
            sum0 += Sf[j][0] + Sf[j][1];
            sum1 += Sf[j][2] + Sf[j][3];
        }
        #pragma unroll
        for (int off = 1; off < 4; off <<= 1) {
            sum0 += __shfl_xor_sync(0xffffffffu, sum0, off);
            sum1 += __shfl_xor_sync(0xffffffffu, sum1, off);
        }
        l0 = l0 * sc0 + sum0;
        l1 = l1 * sc1 + sum1;
        #pragma unroll
        for (int j = 0; j < 8; j++) {
            O[j][0] *= sc0; O[j][1] *= sc0;
            O[j][2] *= sc1; O[j][3] *= sc1;
        }

        // ---- O += P V (bf16x3), interleaved chains ----
        const uint32_t uV = ub + VOFF;
        #pragma unroll
        for (int c = 0; c < 4; c++) {
            uint32_t ph[4], pl[4];
            packhl(Sf[2 * c][0],     Sf[2 * c][1],     ph[0], pl[0]);
            packhl(Sf[2 * c][2],     Sf[2 * c][3],     ph[1], pl[1]);
            packhl(Sf[2 * c + 1][0], Sf[2 * c + 1][1], ph[2], pl[2]);
            packhl(Sf[2 * c + 1][2], Sf[2 * c + 1][3], ph[3], pl[3]);
            #pragma unroll
            for (int jp = 0; jp < 4; jp++) {
                const int mrow = 8 * (2 * jp + ((lane >> 4) & 1)) + (lane & 7);
                const int mcol = 16 * c + ((lane >> 3) & 1) * 8;
                const uint32_t ad = uV + mrow * VSTR + mcol * 2;
                uint32_t vh[4], vl[4];
                ldm_x4(vh, ad);
                ldm_x4(vl, ad + VARR);
                // width-2 interleave, per-acc order hh -> hl -> lh preserved
                mma_bf16(O[2 * jp],     ph, &vh[0]);
                mma_bf16(O[2 * jp + 1], ph, &vh[2]);
                mma_bf16(O[2 * jp],     ph, &vl[0]);
                mma_bf16(O[2 * jp + 1], ph, &vl[2]);
                mma_bf16(O[2 * jp],     pl, &vh[0]);
                mma_bf16(O[2 * jp + 1], pl, &vh[2]);
            }
        }
    }

    // ---- normalize + write split bf16 ----
    const float inv0 = 1.0f / l0, inv1 = 1.0f / l1;
    const size_t rbase = (size_t)(b * Nn + q0 + w * 16) * Dn + h * HDn;
    #pragma unroll
    for (int j = 0; j < 8; j++) {
        const int col = 8 * j + 2 * tg;
        uint32_t hv, lv;
        packhl(O[j][0] * inv0, O[j][1] * inv0, hv, lv);
        *reinterpret_cast<uint32_t*>(&g_oh[rbase + (size_t)g * Dn + col]) = hv;
        *reinterpret_cast<uint32_t*>(&g_ol[rbase + (size_t)g * Dn + col]) = lv;
        packhl(O[j][2] * inv1, O[j][3] * inv1, hv, lv);
        *reinterpret_cast<uint32_t*>(&g_oh[rbase + (size_t)(g + 8) * Dn + col]) = hv;
        *reinterpret_cast<uint32_t*>(&g_ol[rbase + (size_t)(g + 8) * Dn + col]) = lv;
    }
}

// ---------------------------------------------------------------------------
// Launch. Inputs (metadata order): q, mask, attn_bias, Wq, Wk, Wv, Wo
// ---------------------------------------------------------------------------
extern "C" void kernel_launch(void* const* d_in, const int* in_sizes, int n_in,
                              void* d_out, int out_size) {
    const float* q    = (const float*)d_in[0];
    const int*   mask = (const int*)d_in[1];
    const float* bias = (const float*)d_in[2];
    const float* Wq   = (const float*)d_in[3];
    const float* Wk   = (const float*)d_in[4];
    const float* Wv   = (const float*)d_in[5];
    const float* Wo   = (const float*)d_in[6];
    float* out = (float*)d_out;

    cudaFuncSetAttribute(gemm_qkv, cudaFuncAttributeMaxDynamicSharedMemorySize, SMEM_GEMM);
    cudaFuncSetAttribute(gemm_out, cudaFuncAttributeMaxDynamicSharedMemorySize, SMEM_GEMM);
    cudaFuncSetAttribute(attn_mma, cudaFuncAttributeMaxDynamicSharedMemorySize, SMEM_ATT);

    mask_prep<<<32, 256>>>(mask);
    prep_split_x<<<MT * Dn / 4 / 256, 256>>>((const float4*)q);
    prep_split_w<<<dim3(Dn * Dn / 4 / 256, 4), 256>>>(
        (const float4*)Wq, (const float4*)Wk, (const float4*)Wv, (const float4*)Wo);

    gemm_qkv<<<dim3(Dn / 128, MT / 128, 3), 256, SMEM_GEMM>>>();

    attn_mma<<<dim3(Hn, Nn / 128, Bn), 256, SMEM_ATT>>>(bias);

    gemm_out<<<dim3(Dn / 128, MT / 128, 1), 256, SMEM_GEMM>>>(out);
}

// round 11
// speedup vs baseline: 1.0559x; 1.0559x over previous
#include <cuda_runtime.h>
#include <cuda_bf16.h>
#include <cstdint>

// Problem constants
#define Bn  4
#define Nn  2048
#define Dn  512
#define Hn  8
#define HDn 64
#define MT  (Bn*Nn)   // 8192 rows

// Scratch (allocation-free rule: __device__ globals)
__device__ __nv_bfloat16 g_xh[MT*Dn], g_xl[MT*Dn];           // input q split
__device__ __nv_bfloat16 g_wh[4*Dn*Dn], g_wl[4*Dn*Dn];       // Wq,Wk,Wv,Wo split
__device__ __nv_bfloat16 g_qh[MT*Dn], g_ql[MT*Dn];           // Q proj (scaled 1/8)
__device__ __nv_bfloat16 g_kh[MT*Dn], g_kl[MT*Dn];           // K proj [tok][dim]
__device__ __nv_bfloat16 g_vth[MT*Dn], g_vtl[MT*Dn];         // V proj transposed [(b,h,d)][tok]
__device__ __nv_bfloat16 g_oh[MT*Dn], g_ol[MT*Dn];           // attention output split
__device__ float g_maskf[Bn*Nn];

// ===========================================================================
// common helpers
// ===========================================================================
__device__ __forceinline__ uint32_t smem_u32(const void* p) {
    uint32_t a;
    asm("{ .reg .u64 t; cvta.to.shared.u64 t, %1; cvt.u32.u64 %0, t; }" : "=r"(a) : "l"(p));
    return a;
}
__device__ __forceinline__ void mma_bf16(float* c, const uint32_t* a, const uint32_t* b) {
    asm volatile("mma.sync.aligned.m16n8k16.row.col.f32.bf16.bf16.f32 "
        "{%0,%1,%2,%3}, {%4,%5,%6,%7}, {%8,%9}, {%0,%1,%2,%3};"
        : "+f"(c[0]), "+f"(c[1]), "+f"(c[2]), "+f"(c[3])
        : "r"(a[0]), "r"(a[1]), "r"(a[2]), "r"(a[3]), "r"(b[0]), "r"(b[1]));
}
__device__ __forceinline__ void ldm_x4(uint32_t* r, uint32_t saddr) {
    asm volatile("ldmatrix.sync.aligned.m8n8.x4.shared.b16 {%0,%1,%2,%3}, [%4];"
        : "=r"(r[0]), "=r"(r[1]), "=r"(r[2]), "=r"(r[3]) : "r"(saddr));
}
__device__ __forceinline__ void cp16(uint32_t saddr, const void* g) {
    asm volatile("cp.async.ca.shared.global [%0], [%1], 16;" :: "r"(saddr), "l"(g));
}
__device__ __forceinline__ void cp_commit() { asm volatile("cp.async.commit_group;" ::: "memory"); }
__device__ __forceinline__ void cp_wait0()  { asm volatile("cp.async.wait_group 0;" ::: "memory"); }
__device__ __forceinline__ void cp_wait1()  { asm volatile("cp.async.wait_group 1;" ::: "memory"); }

__device__ __forceinline__ uint32_t packbf_hi(float x, float y, float& rx, float& ry) {
    __nv_bfloat16 hx = __float2bfloat16(x), hy = __float2bfloat16(y);
    rx = x - __bfloat162float(hx);
    ry = y - __bfloat162float(hy);
    return (uint32_t)__bfloat16_as_ushort(hx) | ((uint32_t)__bfloat16_as_ushort(hy) << 16);
}
__device__ __forceinline__ uint32_t packbf(float x, float y) {
    return (uint32_t)__bfloat16_as_ushort(__float2bfloat16(x)) |
           ((uint32_t)__bfloat16_as_ushort(__float2bfloat16(y)) << 16);
}
__device__ __forceinline__ void packhl(float x, float y, uint32_t& h, uint32_t& l) {
    float rx, ry;
    h = packbf_hi(x, y, rx, ry);
    l = packbf(rx, ry);
}

// ===========================================================================
// prep: mask -> float addend; fp32 -> bf16 hi/lo split
// ===========================================================================
__global__ void mask_prep(const int* __restrict__ mask) {
    int i = blockIdx.x * blockDim.x + threadIdx.x;
    if (i < Bn * Nn) g_maskf[i] = mask[i] ? -1e30f : 0.0f;
}

__global__ void prep_split_x(const float4* __restrict__ src) {
    int i = blockIdx.x * blockDim.x + threadIdx.x;      // over MT*Dn/4
    float4 v = src[i];
    float r0, r1, r2, r3;
    uint32_t h0 = packbf_hi(v.x, v.y, r0, r1);
    uint32_t h1 = packbf_hi(v.z, v.w, r2, r3);
    reinterpret_cast<uint2*>(g_xh)[i] = make_uint2(h0, h1);
    reinterpret_cast<uint2*>(g_xl)[i] = make_uint2(packbf(r0, r1), packbf(r2, r3));
}

__global__ void prep_split_w(const float4* __restrict__ w0, const float4* __restrict__ w1,
                             const float4* __restrict__ w2, const float4* __restrict__ w3) {
    int i = blockIdx.x * blockDim.x + threadIdx.x;      // over Dn*Dn/4
    int z = blockIdx.y;
    const float4* src = (z == 0) ? w0 : (z == 1) ? w1 : (z == 2) ? w2 : w3;
    float4 v = src[i];
    float r0, r1, r2, r3;
    uint32_t h0 = packbf_hi(v.x, v.y, r0, r1);
    uint32_t h1 = packbf_hi(v.z, v.w, r2, r3);
    size_t o = (size_t)z * (Dn * Dn / 4) + i;
    reinterpret_cast<uint2*>(g_wh)[o] = make_uint2(h0, h1);
    reinterpret_cast<uint2*>(g_wl)[o] = make_uint2(packbf(r0, r1), packbf(r2, r3));
}

// ===========================================================================
// bf16x3 GEMM: CTA tile 256x128, 8 warps as 4(m) x 2(n), warp tile 64x64.
// BK=32, 2-stage cp.async double buffer, ldmatrix loads, 1 CTA/SM.
// Per-warp per k16: 8 A-ldm + 8 B-ldm for 96 MMAs (0.167 ldm/MMA).
// ===========================================================================
#define BK    32
#define SAstr 40                    // bf16 elems per smem row (80 B)
#define GA_AH 0
#define GA_AL 20480                 // 256*80
#define GA_BH 40960
#define GA_BL 51200                 // +128*80
#define GSTG  61440
#define SMEM_GEMM (2*GSTG)          // 122880 B
#define NCH   (Dn/BK)               // 16

#define GEMM_MAINLOOP(AH, AL, BH, BL, ACC) \
    const uint32_t sU = smem_u32(smg); \
    const __nv_bfloat16* Ah_g = (AH) + (size_t)m0 * Dn; \
    const __nv_bfloat16* Al_g = (AL) + (size_t)m0 * Dn; \
    const __nv_bfloat16* Bh_g = (BH) + (size_t)n0 * Dn; \
    const __nv_bfloat16* Bl_g = (BL) + (size_t)n0 * Dn; \
    auto prefetch = [&](int kc) { \
        const uint32_t u = sU + (kc & 1) * GSTG; \
        _Pragma("unroll") \
        for (int t = 0; t < 4; t++) {                /* A: 256 rows x 4 chunks */ \
            int id = tid + t * 256; \
            int row = id >> 2, c = id & 3; \
            size_t go = (size_t)row * Dn + kc * BK + c * 8; \
            uint32_t so = u + row * (SAstr * 2) + c * 16; \
            cp16(so + GA_AH, Ah_g + go); \
            cp16(so + GA_AL, Al_g + go); \
        } \
        _Pragma("unroll") \
        for (int t = 0; t < 2; t++) {                /* B: 128 rows x 4 chunks */ \
            int id = tid + t * 256; \
            int row = id >> 2, c = id & 3; \
            size_t go = (size_t)row * Dn + kc * BK + c * 8; \
            uint32_t so = u + row * (SAstr * 2) + c * 16; \
            cp16(so + GA_BH, Bh_g + go); \
            cp16(so + GA_BL, Bl_g + go); \
        } \
        cp_commit(); \
    }; \
    prefetch(0); \
    _Pragma("unroll 1") \
    for (int kc = 0; kc < NCH; kc++) { \
        if (kc + 1 < NCH) { prefetch(kc + 1); cp_wait1(); } else { cp_wait0(); } \
        __syncthreads(); \
        const uint32_t s = sU + (kc & 1) * GSTG; \
        _Pragma("unroll") \
        for (int ks = 0; ks < 2; ks++) { \
            const int k0 = ks * 16; \
            uint32_t ah[4][4], al[4][4]; \
            _Pragma("unroll") \
            for (int t = 0; t < 4; t++) { \
                uint32_t ra = wm + t * 16 + (lane & 15); \
                uint32_t ad = s + (ra * SAstr + k0 + (lane >> 4) * 8) * 2; \
                ldm_x4(ah[t], ad + GA_AH); \
                ldm_x4(al[t], ad + GA_AL); \
            } \
            _Pragma("unroll") \
            for (int jj = 0; jj < 4; jj++) { \
                uint32_t rb = wn + 8 * (2 * jj + ((lane >> 4) & 1)) + (lane & 7); \
                uint32_t ad = s + (rb * SAstr + k0 + ((lane >> 3) & 1) * 8) * 2; \
                uint32_t bh[4], bl[4]; \
                ldm_x4(bh, ad + GA_BH); \
                ldm_x4(bl, ad + GA_BL); \
                _Pragma("unroll") \
                for (int t = 0; t < 4; t++) { \
                    mma_bf16(ACC[t][2 * jj],     ah[t], &bh[0]); \
                    mma_bf16(ACC[t][2 * jj],     ah[t], &bl[0]); \
                    mma_bf16(ACC[t][2 * jj],     al[t], &bh[0]); \
                    mma_bf16(ACC[t][2 * jj + 1], ah[t], &bh[2]); \
                    mma_bf16(ACC[t][2 * jj + 1], ah[t], &bl[2]); \
                    mma_bf16(ACC[t][2 * jj + 1], al[t], &bh[2]); \
                } \
            } \
        } \
        __syncthreads(); \
    }

// ---------------------------------------------------------------------------
// QKV projection GEMM: z=0 Q (scaled 1/8), z=1 K, z=2 V (smem-transposed)
// ---------------------------------------------------------------------------
#define TSTR2 264    // V-transpose smem: tokens per d-row (528 B, 16B-mult)

__global__ __launch_bounds__(256, 1) void gemm_qkv() {
    extern __shared__ __align__(16) char smg[];
    const int tid  = threadIdx.x;
    const int lane = tid & 31;
    const int g    = lane >> 2;
    const int tg   = lane & 3;
    const int wid  = tid >> 5;
    const int n0 = blockIdx.x * 128, m0 = blockIdx.y * 256;
    const int z  = blockIdx.z;
    const int wm = (wid & 3) * 64;     // 4 warps along M (256)
    const int wn = (wid >> 2) * 64;    // 2 warps along N (128)

    float acc[4][8][4];
    #pragma unroll
    for (int t = 0; t < 4; t++)
        #pragma unroll
        for (int j = 0; j < 8; j++)
            #pragma unroll
            for (int e = 0; e < 4; e++) acc[t][j][e] = 0.0f;

    const __nv_bfloat16* Wh = g_wh + (size_t)z * Dn * Dn;
    const __nv_bfloat16* Wl = g_wl + (size_t)z * Dn * Dn;
    GEMM_MAINLOOP(g_xh, g_xl, Wh, Wl, acc)

    if (z < 2) {
        __nv_bfloat16* Oh = (z == 0) ? g_qh : g_kh;
        __nv_bfloat16* Ol = (z == 0) ? g_ql : g_kl;
        const float sc = (z == 0) ? 0.125f : 1.0f;
        #pragma unroll
        for (int t = 0; t < 4; t++)
            #pragma unroll
            for (int j = 0; j < 8; j++) {
                int r = m0 + wm + t * 16 + g;
                int c = n0 + wn + j * 8 + tg * 2;
                float v0 = acc[t][j][0] * sc, v1 = acc[t][j][1] * sc;
                float v2 = acc[t][j][2] * sc, v3 = acc[t][j][3] * sc;
                uint32_t h, l;
                packhl(v0, v1, h, l);
                *reinterpret_cast<uint32_t*>(&Oh[(size_t)r * Dn + c]) = h;
                *reinterpret_cast<uint32_t*>(&Ol[(size_t)r * Dn + c]) = l;
                packhl(v2, v3, h, l);
                *reinterpret_cast<uint32_t*>(&Oh[(size_t)(r + 8) * Dn + c]) = h;
                *reinterpret_cast<uint32_t*>(&Ol[(size_t)(r + 8) * Dn + c]) = l;
            }
    } else {
        // V: transpose through smem in two passes (hi then lo), coalesced out
        #pragma unroll
        for (int pass = 0; pass < 2; pass++) {
            __syncthreads();
            #pragma unroll
            for (int t = 0; t < 4; t++)
                #pragma unroll
                for (int j = 0; j < 8; j++)
                    #pragma unroll
                    for (int e = 0; e < 4; e++) {
                        int lr = wm + t * 16 + g + (e >> 1) * 8;   // local token 0..255
                        int lc = wn + j * 8 + tg * 2 + (e & 1);    // local dim 0..127
                        float v = acc[t][j][e];
                        __nv_bfloat16 hv = __float2bfloat16(v);
                        __nv_bfloat16 sv = pass ? __float2bfloat16(v - __bfloat162float(hv)) : hv;
                        *reinterpret_cast<__nv_bfloat16*>(smg + (size_t)lc * (TSTR2 * 2) + lr * 2) = sv;
                    }
            __syncthreads();
            const int dd = tid >> 1;          // 0..127 (local dim)
            const int hf = tid & 1;           // token half (128 each)
            const int b  = m0 >> 11;
            const int hh = (n0 + dd) >> 6;
            const int d  = (n0 + dd) & 63;
            __nv_bfloat16* dstp = pass ? g_vtl : g_vth;
            const size_t dst = (((size_t)(b * Hn + hh)) * HDn + d) * Nn + (m0 & (Nn - 1)) + hf * 128;
            const uint32_t so = (uint32_t)dd * (TSTR2 * 2) + hf * 256;
            #pragma unroll
            for (int u = 0; u < 16; u++)
                *reinterpret_cast<uint4*>(&dstp[dst + u * 8]) =
                    *reinterpret_cast<const uint4*>(smg + so + u * 16);
        }
    }
}

// ---------------------------------------------------------------------------
// Output projection GEMM: reads pre-split O, writes fp32
// ---------------------------------------------------------------------------
__global__ __launch_bounds__(256, 1) void gemm_out(float* __restrict__ C) {
    extern __shared__ __align__(16) char smg[];
    const int tid  = threadIdx.x;
    const int lane = tid & 31;
    const int g    = lane >> 2;
    const int tg   = lane & 3;
    const int wid  = tid >> 5;
    const int n0 = blockIdx.x * 128, m0 = blockIdx.y * 256;
    const int wm = (wid & 3) * 64;
    const int wn = (wid >> 2) * 64;

    float acc[4][8][4];
    #pragma unroll
    for (int t = 0; t < 4; t++)
        #pragma unroll
        for (int j = 0; j < 8; j++)
            #pragma unroll
            for (int e = 0; e < 4; e++) acc[t][j][e] = 0.0f;

    const __nv_bfloat16* Wh = g_wh + (size_t)3 * Dn * Dn;
    const __nv_bfloat16* Wl = g_wl + (size_t)3 * Dn * Dn;
    GEMM_MAINLOOP(g_oh, g_ol, Wh, Wl, acc)

    #pragma unroll
    for (int t = 0; t < 4; t++)
        #pragma unroll
        for (int j = 0; j < 8; j++) {
            int row = m0 + wm + t * 16 + g;
            int col = n0 + wn + j * 8 + tg * 2;
            *reinterpret_cast<float2*>(C + (size_t)row * Dn + col) =
                make_float2(acc[t][j][0], acc[t][j][1]);
            *reinterpret_cast<float2*>(C + (size_t)(row + 8) * Dn + col) =
                make_float2(acc[t][j][2], acc[t][j][3]);
        }
}

// ===========================================================================
// Tensor-core flash attention (R9 version): 128 q-rows per CTA (8 warps),
// k-tiles of 64 keys, bf16x3 S and PV, cp.async double buffer, 2 CTAs/SM.
// ===========================================================================
#define KSTR 144
#define VSTR 144
#define KARR (64*KSTR)
#define VARR (64*VSTR)
#define VOFF (2*KARR)
#define MOFF (2*KARR + 2*VARR)
#define STG_ATT (MOFF + 256)
#define SMEM_ATT (2*STG_ATT)

__global__ __launch_bounds__(256, 2) void attn_mma(const float* __restrict__ bias) {
    extern __shared__ __align__(16) char sma[];
    const uint32_t sb = smem_u32(sma);
    const int tid  = threadIdx.x;
    const int lane = tid & 31;
    const int w    = tid >> 5;
    const int g    = lane >> 2;
    const int tg   = lane & 3;
    const int h  = blockIdx.x;
    const int q0 = blockIdx.y * 128;
    const int b  = blockIdx.z;

    // ---- Q fragments from gmem (once) ----
    uint32_t qh[4][4], ql[4][4];
    {
        const size_t rbase = (size_t)(b * Nn + q0 + w * 16) * Dn + h * HDn;
        #pragma unroll
        for (int c = 0; c < 4; c++) {
            size_t o0 = rbase + (size_t)g * Dn + c * 16 + tg * 2;
            size_t o1 = rbase + (size_t)(g + 8) * Dn + c * 16 + tg * 2;
            qh[c][0] = *reinterpret_cast<const uint32_t*>(&g_qh[o0]);
            qh[c][1] = *reinterpret_cast<const uint32_t*>(&g_qh[o1]);
            qh[c][2] = *reinterpret_cast<const uint32_t*>(&g_qh[o0 + 8]);
            qh[c][3] = *reinterpret_cast<const uint32_t*>(&g_qh[o1 + 8]);
            ql[c][0] = *reinterpret_cast<const uint32_t*>(&g_ql[o0]);
            ql[c][1] = *reinterpret_cast<const uint32_t*>(&g_ql[o1]);
            ql[c][2] = *reinterpret_cast<const uint32_t*>(&g_ql[o0 + 8]);
            ql[c][3] = *reinterpret_cast<const uint32_t*>(&g_ql[o1 + 8]);
        }
    }

    const char* kh_base = (const char*)g_kh + ((size_t)(b * Nn) * Dn + h * HDn) * 2;
    const char* kl_base = (const char*)g_kl + ((size_t)(b * Nn) * Dn + h * HDn) * 2;
    const char* vh_base = (const char*)g_vth + ((size_t)(b * Hn + h) * HDn) * Nn * 2;
    const char* vl_base = (const char*)g_vtl + ((size_t)(b * Hn + h) * HDn) * Nn * 2;
    const char* mk_base = (const char*)g_maskf + (size_t)(b * Nn) * 4;

    auto prefetch = [&](int kt) {
        const uint32_t u = sb + (kt & 1) * STG_ATT;
        const size_t kof = (size_t)kt * 64 * (Dn * 2);
        #pragma unroll
        for (int t = 0; t < 2; t++) {
            int id = tid + t * 256;
            int row = id >> 3, c = id & 7;
            cp16(u + row * KSTR + c * 16,        kh_base + kof + (size_t)row * (Dn * 2) + c * 16);
            cp16(u + KARR + row * KSTR + c * 16, kl_base + kof + (size_t)row * (Dn * 2) + c * 16);
            cp16(u + VOFF + row * VSTR + c * 16,
                 vh_base + (size_t)row * (Nn * 2) + kt * 128 + c * 16);
            cp16(u + VOFF + VARR + row * VSTR + c * 16,
                 vl_base + (size_t)row * (Nn * 2) + kt * 128 + c * 16);
        }
        if (tid < 16) cp16(u + MOFF + tid * 16, mk_base + (size_t)kt * 256 + tid * 16);
        cp_commit();
    };

    float O[8][4];
    #pragma unroll
    for (int j = 0; j < 8; j++)
        #pragma unroll
        for (int e = 0; e < 4; e++) O[j][e] = 0.0f;
    float m0r = -3e38f, m1r = -3e38f, l0 = 0.0f, l1 = 0.0f;

    prefetch(0);

    const float* bb = bias + ((size_t)(b * Nn) + q0 + w * 16) * Nn;

    #pragma unroll 1
    for (int kt = 0; kt < Nn / 64; kt++) {
        cp_wait0();
        __syncthreads();
        const uint32_t u = sb + (kt & 1) * STG_ATT;
        if (kt + 1 < Nn / 64) prefetch(kt + 1);

        // ---- S = Q K^T (bf16x3) ----
        float Sf[8][4];
        #pragma unroll
        for (int j = 0; j < 8; j++)
            #pragma unroll
            for (int e = 0; e < 4; e++) Sf[j][e] = 0.0f;

        #pragma unroll
        for (int c = 0; c < 4; c++) {
            #pragma unroll
            for (int jp = 0; jp < 4; jp++) {
                const int mrow = 8 * (2 * jp + ((lane >> 4) & 1)) + (lane & 7);
                const int mcol = 16 * c + ((lane >> 3) & 1) * 8;
                const uint32_t ad = u + mrow * KSTR + mcol * 2;
                uint32_t bh[4], bl[4];
                ldm_x4(bh, ad);
                ldm_x4(bl, ad + KARR);
                mma_bf16(Sf[2 * jp],     qh[c], &bh[0]);
                mma_bf16(Sf[2 * jp],     qh[c], &bl[0]);
                mma_bf16(Sf[2 * jp],     ql[c], &bh[0]);
                mma_bf16(Sf[2 * jp + 1], qh[c], &bh[2]);
                mma_bf16(Sf[2 * jp + 1], qh[c], &bl[2]);
                mma_bf16(Sf[2 * jp + 1], ql[c], &bh[2]);
            }
        }

        // ---- bias + mask ----
        const float* bt = bb + (size_t)kt * 64;
        #pragma unroll
        for (int j = 0; j < 8; j++) {
            float2 mv = *reinterpret_cast<const float2*>(sma + (kt & 1) * STG_ATT + MOFF
                                                         + (8 * j + 2 * tg) * 4);
            float2 bv0 = *reinterpret_cast<const float2*>(bt + (size_t)g * Nn + 8 * j + 2 * tg);
            float2 bv1 = *reinterpret_cast<const float2*>(bt + (size_t)(g + 8) * Nn + 8 * j + 2 * tg);
            Sf[j][0] += bv0.x + mv.x; Sf[j][1] += bv0.y + mv.y;
            Sf[j][2] += bv1.x + mv.x; Sf[j][3] += bv1.y + mv.y;
        }

        // ---- online softmax on fragments ----
        float mx0 = -3e38f, mx1 = -3e38f;
        #pragma unroll
        for (int j = 0; j < 8; j++) {
            mx0 = fmaxf(mx0, fmaxf(Sf[j][0], Sf[j][1]));
            mx1 = fmaxf(mx1, fmaxf(Sf[j][2], Sf[j][3]));
        }
        #pragma unroll
        for (int off = 1; off < 4; off <<= 1) {
            mx0 = fmaxf(mx0, __shfl_xor_sync(0xffffffffu, mx0, off));
            mx1 = fmaxf(mx1, __shfl_xor_sync(0xffffffffu, mx1, off));
        }
        const float mn0 = fmaxf(m0r, mx0), mn1 = fmaxf(m1r, mx1);
        const float sc0 = __expf(m0r - mn0), sc1 = __expf(m1r - mn1);
        m0r = mn0; m1r = mn1;
        float sum0 = 0.0f, sum1 = 0.0f;
        #pragma unroll
        for (int j = 0; j < 8; j++) {
            Sf[j][0] = __expf(Sf[j][0] - mn0);
            Sf[j][1] = __expf(Sf[j][1] - mn0);
            Sf[j][2] = __expf(Sf[j][2] - mn1);
            Sf[j][3] = __expf(Sf[j][3] - mn1);
            sum0 += Sf[j][0] + Sf[j][1];
            sum1 += Sf[j][2] + Sf[j][3];
        }
        #pragma unroll
        for (int off = 1; off < 4; off <<= 1) {
            sum0 += __shfl_xor_sync(0xffffffffu, sum0, off);
            sum1 += __shfl_xor_sync(0xffffffffu, sum1, off);
        }
        l0 = l0 * sc0 + sum0;
        l1 = l1 * sc1 + sum1;
        #pragma unroll
        for (int j = 0; j < 8; j++) {
            O[j][0] *= sc0; O[j][1] *= sc0;
            O[j][2] *= sc1; O[j][3] *= sc1;
        }

        // ---- O += P V (bf16x3) ----
        const uint32_t uV = u + VOFF;
        #pragma unroll
        for (int c = 0; c < 4; c++) {
            uint32_t ph[4], pl[4];
            packhl(Sf[2 * c][0],     Sf[2 * c][1],     ph[0], pl[0]);
            packhl(Sf[2 * c][2],     Sf[2 * c][3],     ph[1], pl[1]);
            packhl(Sf[2 * c + 1][0], Sf[2 * c + 1][1], ph[2], pl[2]);
            packhl(Sf[2 * c + 1][2], Sf[2 * c + 1][3], ph[3], pl[3]);
            #pragma unroll
            for (int jp = 0; jp < 4; jp++) {
                const int mrow = 8 * (2 * jp + ((lane >> 4) & 1)) + (lane & 7);
                const int mcol = 16 * c + ((lane >> 3) & 1) * 8;
                const uint32_t ad = uV + mrow * VSTR + mcol * 2;
                uint32_t vh[4], vl[4];
                ldm_x4(vh, ad);
                ldm_x4(vl, ad + VARR);
                mma_bf16(O[2 * jp],     ph, &vh[0]);
                mma_bf16(O[2 * jp],     ph, &vl[0]);
                mma_bf16(O[2 * jp],     pl, &vh[0]);
                mma_bf16(O[2 * jp + 1], ph, &vh[2]);
                mma_bf16(O[2 * jp + 1], ph, &vl[2]);
                mma_bf16(O[2 * jp + 1], pl, &vh[2]);
            }
        }
    }

    // ---- normalize + write split bf16 ----
    const float inv0 = 1.0f / l0, inv1 = 1.0f / l1;
    const size_t rbase = (size_t)(b * Nn + q0 + w * 16) * Dn + h * HDn;
    #pragma unroll
    for (int j = 0; j < 8; j++) {
        const int col = 8 * j + 2 * tg;
        uint32_t hv, lv;
        packhl(O[j][0] * inv0, O[j][1] * inv0, hv, lv);
        *reinterpret_cast<uint32_t*>(&g_oh[rbase + (size_t)g * Dn + col]) = hv;
        *reinterpret_cast<uint32_t*>(&g_ol[rbase + (size_t)g * Dn + col]) = lv;
        packhl(O[j][2] * inv1, O[j][3] * inv1, hv, lv);
        *reinterpret_cast<uint32_t*>(&g_oh[rbase + (size_t)(g + 8) * Dn + col]) = hv;
        *reinterpret_cast<uint32_t*>(&g_ol[rbase + (size_t)(g + 8) * Dn + col]) = lv;
    }
}

// ---------------------------------------------------------------------------
// Launch. Inputs (metadata order): q, mask, attn_bias, Wq, Wk, Wv, Wo
// ---------------------------------------------------------------------------
extern "C" void kernel_launch(void* const* d_in, const int* in_sizes, int n_in,
                              void* d_out, int out_size) {
    const float* q    = (const float*)d_in[0];
    const int*   mask = (const int*)d_in[1];
    const float* bias = (const float*)d_in[2];
    const float* Wq   = (const float*)d_in[3];
    const float* Wk   = (const float*)d_in[4];
    const float* Wv   = (const float*)d_in[5];
    const float* Wo   = (const float*)d_in[6];
    float* out = (float*)d_out;

    cudaFuncSetAttribute(gemm_qkv, cudaFuncAttributeMaxDynamicSharedMemorySize, SMEM_GEMM);
    cudaFuncSetAttribute(gemm_out, cudaFuncAttributeMaxDynamicSharedMemorySize, SMEM_GEMM);
    cudaFuncSetAttribute(attn_mma, cudaFuncAttributeMaxDynamicSharedMemorySize, SMEM_ATT);

    mask_prep<<<32, 256>>>(mask);
    prep_split_x<<<MT * Dn / 4 / 256, 256>>>((const float4*)q);
    prep_split_w<<<dim3(Dn * Dn / 4 / 256, 4), 256>>>(
        (const float4*)Wq, (const float4*)Wk, (const float4*)Wv, (const float4*)Wo);

    gemm_qkv<<<dim3(Dn / 128, MT / 256, 3), 256, SMEM_GEMM>>>();

    attn_mma<<<dim3(Hn, Nn / 128, Bn), 256, SMEM_ATT>>>(bias);

    gemm_out<<<dim3(Dn / 128, MT / 256, 1), 256, SMEM_GEMM>>>(out);
}